// round 1
// baseline (speedup 1.0000x reference)
#include <cuda_runtime.h>

// Problem constants
#define BB 32
#define NN 4096
#define DD 1024
#define HH 16

// Scratch (device globals — no allocations allowed)
__device__ float g_q[BB * DD];            // q projection  [B][H*64]
__device__ float g_U[BB * HH * DD];       // folded key-side vectors [B][H][D] (scaled by 1/8)
__device__ float g_att[BB * HH * NN];     // scores -> attn (softmaxed in place)
__device__ float g_wp[4][BB * HH * DD];   // partial attn@value over 4 n-segments
__device__ float g_w[BB * HH * DD];       // summed attn@value

typedef unsigned long long u64;

__device__ __forceinline__ void fma2(u64 &d, u64 a, u64 b) {
    asm("fma.rn.f32x2 %0, %1, %2, %0;" : "+l"(d) : "l"(a), "l"(b));
}
__device__ __forceinline__ u64 pack2(float lo, float hi) {
    u64 r; asm("mov.b64 %0, {%1, %2};" : "=l"(r) : "f"(lo), "f"(hi)); return r;
}
__device__ __forceinline__ void unpack2(u64 v, float &lo, float &hi) {
    asm("mov.b64 {%0, %1}, %2;" : "=f"(lo), "=f"(hi) : "l"(v));
}

// ---------------------------------------------------------------------------
// Kernel A: q[b,c] = sum_i query[b,i] * wq[i,c]      (tiny: 32x1024 output)
// ---------------------------------------------------------------------------
__global__ __launch_bounds__(256) void k_qproj(const float* __restrict__ query,
                                               const float* __restrict__ wq) {
    int b = blockIdx.y;
    int c = blockIdx.x * 256 + threadIdx.x;
    __shared__ float sq[DD];
    for (int i = threadIdx.x; i < DD; i += 256) sq[i] = query[b * DD + i];
    __syncthreads();
    float acc = 0.f;
#pragma unroll 8
    for (int i = 0; i < DD; i++) acc = fmaf(sq[i], wq[i * DD + c], acc);
    g_q[b * DD + c] = acc;
}

// ---------------------------------------------------------------------------
// Kernel B: U[b,h,d] = (1/8) * sum_{j<64} wk[d, h*64+j] * q[b, h*64+j]
// block: (d-tile of 128, b), 128 threads (one per d)
// ---------------------------------------------------------------------------
__global__ __launch_bounds__(128) void k_uproj(const float* __restrict__ wk) {
    int b  = blockIdx.y;
    int d0 = blockIdx.x * 128;
    int tx = threadIdx.x;
    __shared__ float swk[128 * 33];
    __shared__ float sq[DD];
    for (int i = tx; i < DD; i += 128) sq[i] = g_q[b * DD + i];

    int cc = tx & 31;
    int r0 = (tx >> 5) * 32;
    for (int h = 0; h < HH; h++) {
        float a = 0.f;
        for (int sub = 0; sub < 2; sub++) {
            int c0 = h * 64 + sub * 32;
            __syncthreads();
#pragma unroll
            for (int it = 0; it < 32; it++) {
                int r = r0 + it;
                swk[r * 33 + cc] = wk[(d0 + r) * DD + c0 + cc];
            }
            __syncthreads();
#pragma unroll
            for (int c2 = 0; c2 < 32; c2++)
                a = fmaf(swk[tx * 33 + c2], sq[c0 + c2], a);
        }
        g_U[(b * HH + h) * DD + d0 + tx] = a * 0.125f;
    }
}

// ---------------------------------------------------------------------------
// Kernel C: scores[b,h,n] = sum_d key[b,n,d] * U[b,h,d]   (streams key: 512 MB)
// block: (n-tile of 256, b), 256 threads; thread owns one n, 16 head accs
// packed into 8 f32x2 registers (head pairs).
// ---------------------------------------------------------------------------
__global__ __launch_bounds__(256) void k_scores(const float* __restrict__ key) {
    const int tx = threadIdx.x;
    const int b  = blockIdx.y;
    const int n0 = blockIdx.x * 256;

    __shared__ __align__(16) float sk[256 * 33];
    __shared__ __align__(16) float sU[32 * 20];

    u64 acc[8];
#pragma unroll
    for (int p = 0; p < 8; p++) acc[p] = 0ull;

    const float* keyb = key + ((size_t)b * NN + n0) * DD;

    for (int ch = 0; ch < 32; ch++) {
        int d0 = ch * 32;
        __syncthreads();
        // stage key tile [256 n][32 d], coalesced float4 loads, padded smem
#pragma unroll
        for (int it = 0; it < 8; it++) {
            int fl = it * 256 + tx;
            int n  = fl >> 3;
            int q4 = (fl & 7) * 4;
            float4 v = *reinterpret_cast<const float4*>(keyb + (size_t)n * DD + d0 + q4);
            sk[n * 33 + q4 + 0] = v.x;
            sk[n * 33 + q4 + 1] = v.y;
            sk[n * 33 + q4 + 2] = v.z;
            sk[n * 33 + q4 + 3] = v.w;
        }
        // stage U chunk [32 d][16 h], stride 20 words keeps 16B alignment per row
        {
            int dd = tx & 31, h8 = tx >> 5;
            sU[dd * 20 + h8]     = g_U[(b * HH + h8) * DD + d0 + dd];
            sU[dd * 20 + h8 + 8] = g_U[(b * HH + h8 + 8) * DD + d0 + dd];
        }
        __syncthreads();

#pragma unroll 8
        for (int dd = 0; dd < 32; dd++) {
            float kv = sk[tx * 33 + dd];
            u64 kv2 = pack2(kv, kv);
            const ulonglong2* uv = reinterpret_cast<const ulonglong2*>(&sU[dd * 20]);
            ulonglong2 ua = uv[0];  // heads (0,1),(2,3)
            ulonglong2 ub = uv[1];  // heads (4,5),(6,7)
            fma2(acc[0], ua.x, kv2);
            fma2(acc[1], ua.y, kv2);
            fma2(acc[2], ub.x, kv2);
            fma2(acc[3], ub.y, kv2);
            ulonglong2 uc = uv[2];  // heads (8,9),(10,11)
            ulonglong2 ud = uv[3];  // heads (12,13),(14,15)
            fma2(acc[4], uc.x, kv2);
            fma2(acc[5], uc.y, kv2);
            fma2(acc[6], ud.x, kv2);
            fma2(acc[7], ud.y, kv2);
        }
    }

#pragma unroll
    for (int p = 0; p < 8; p++) {
        float lo, hi;
        unpack2(acc[p], lo, hi);
        g_att[((size_t)b * HH + 2 * p)     * NN + n0 + tx] = lo;
        g_att[((size_t)b * HH + 2 * p + 1) * NN + n0 + tx] = hi;
    }
}

// ---------------------------------------------------------------------------
// Kernel D: in-place softmax over N per (b,h) row. 512 rows.
// ---------------------------------------------------------------------------
__global__ __launch_bounds__(256) void k_softmax() {
    int row = blockIdx.x;
    int tx  = threadIdx.x;
    float* p = g_att + (size_t)row * NN;
    float4* pv = reinterpret_cast<float4*>(p);

    float4 x[4];
#pragma unroll
    for (int i = 0; i < 4; i++) x[i] = pv[i * 256 + tx];

    float m = -3e38f;
#pragma unroll
    for (int i = 0; i < 4; i++) {
        m = fmaxf(m, fmaxf(fmaxf(x[i].x, x[i].y), fmaxf(x[i].z, x[i].w)));
    }
    __shared__ float r1[8], r2[8];
#pragma unroll
    for (int o = 16; o; o >>= 1) m = fmaxf(m, __shfl_xor_sync(0xffffffffu, m, o));
    if ((tx & 31) == 0) r1[tx >> 5] = m;
    __syncthreads();
    float bm = r1[0];
#pragma unroll
    for (int w = 1; w < 8; w++) bm = fmaxf(bm, r1[w]);

    float s = 0.f;
#pragma unroll
    for (int i = 0; i < 4; i++) {
        x[i].x = __expf(x[i].x - bm);
        x[i].y = __expf(x[i].y - bm);
        x[i].z = __expf(x[i].z - bm);
        x[i].w = __expf(x[i].w - bm);
        s += x[i].x + x[i].y + x[i].z + x[i].w;
    }
#pragma unroll
    for (int o = 16; o; o >>= 1) s += __shfl_xor_sync(0xffffffffu, s, o);
    if ((tx & 31) == 0) r2[tx >> 5] = s;
    __syncthreads();
    float tot = 0.f;
#pragma unroll
    for (int w = 0; w < 8; w++) tot += r2[w];
    float inv = 1.f / tot;
#pragma unroll
    for (int i = 0; i < 4; i++) {
        x[i].x *= inv; x[i].y *= inv; x[i].z *= inv; x[i].w *= inv;
        pv[i * 256 + tx] = x[i];
    }
}

// ---------------------------------------------------------------------------
// Kernel E: wp[seg][b,h,d] = sum_{n in seg} attn[b,h,n] * value[b,n,d]
// block: (d-tile 256, n-seg 4, b), 256 threads; thread owns one d.
// value loads are perfectly coalesced straight from gmem (streams value: 512 MB)
// ---------------------------------------------------------------------------
__global__ __launch_bounds__(256) void k_wpart(const float* __restrict__ value) {
    const int tx   = threadIdx.x;
    const int d0   = blockIdx.x * 256;
    const int nseg = blockIdx.y;
    const int b    = blockIdx.z;

    __shared__ __align__(16) float sA[32 * 20];

    u64 acc[8];
#pragma unroll
    for (int p = 0; p < 8; p++) acc[p] = 0ull;

    const float* valb = value + ((size_t)b * NN + nseg * 1024) * DD + d0 + tx;
    const int attbase = nseg * 1024;

    for (int ch = 0; ch < 32; ch++) {
        int n0 = ch * 32;
        __syncthreads();
        {
            int nn = tx & 31, h8 = tx >> 5;
            sA[nn * 20 + h8]     = g_att[((size_t)b * HH + h8)     * NN + attbase + n0 + nn];
            sA[nn * 20 + h8 + 8] = g_att[((size_t)b * HH + h8 + 8) * NN + attbase + n0 + nn];
        }
        __syncthreads();

#pragma unroll 8
        for (int nn2 = 0; nn2 < 32; nn2++) {
            float vv = valb[(size_t)(n0 + nn2) * DD];
            u64 vv2 = pack2(vv, vv);
            const ulonglong2* av = reinterpret_cast<const ulonglong2*>(&sA[nn2 * 20]);
            ulonglong2 aa = av[0];
            ulonglong2 ab = av[1];
            fma2(acc[0], aa.x, vv2);
            fma2(acc[1], aa.y, vv2);
            fma2(acc[2], ab.x, vv2);
            fma2(acc[3], ab.y, vv2);
            ulonglong2 ac = av[2];
            ulonglong2 ad = av[3];
            fma2(acc[4], ac.x, vv2);
            fma2(acc[5], ac.y, vv2);
            fma2(acc[6], ad.x, vv2);
            fma2(acc[7], ad.y, vv2);
        }
    }

#pragma unroll
    for (int p = 0; p < 8; p++) {
        float lo, hi;
        unpack2(acc[p], lo, hi);
        g_wp[nseg][(b * HH + 2 * p)     * DD + d0 + tx] = lo;
        g_wp[nseg][(b * HH + 2 * p + 1) * DD + d0 + tx] = hi;
    }
}

// ---------------------------------------------------------------------------
// Kernel G: fold the 4 n-segment partials: g_w = sum_p g_wp[p]
// ---------------------------------------------------------------------------
__global__ __launch_bounds__(256) void k_wsum() {
    int i = blockIdx.x * 256 + threadIdx.x;  // over B*H*D/4 float4s
    float4 a = reinterpret_cast<float4*>(g_wp[0])[i];
    float4 c = reinterpret_cast<float4*>(g_wp[1])[i];
    float4 e = reinterpret_cast<float4*>(g_wp[2])[i];
    float4 f = reinterpret_cast<float4*>(g_wp[3])[i];
    float4 o;
    o.x = a.x + c.x + e.x + f.x;
    o.y = a.y + c.y + e.y + f.y;
    o.z = a.z + c.z + e.z + f.z;
    o.w = a.w + c.w + e.w + f.w;
    reinterpret_cast<float4*>(g_w)[i] = o;
}

// ---------------------------------------------------------------------------
// Kernel F: out[b,c] = sum_d w[b, c>>6, d] * wv[d, c]
// block: (c-chunk 256 = 4 heads, b), 256 threads
// ---------------------------------------------------------------------------
__global__ __launch_bounds__(256) void k_oproj(const float* __restrict__ wv,
                                               float* __restrict__ out) {
    int b  = blockIdx.y;
    int c  = blockIdx.x * 256 + threadIdx.x;
    int h0 = (blockIdx.x * 256) >> 6;  // first of 4 heads in this chunk
    __shared__ float sw[4 * DD];
    for (int i = threadIdx.x; i < 4 * DD; i += 256)
        sw[i] = g_w[(b * HH + h0) * DD + i];
    __syncthreads();
    const float* swg = sw + ((threadIdx.x >> 6) * DD);
    float acc = 0.f;
#pragma unroll 8
    for (int d = 0; d < DD; d++) acc = fmaf(swg[d], wv[d * DD + c], acc);
    out[b * DD + c] = acc;
}

// ---------------------------------------------------------------------------
extern "C" void kernel_launch(void* const* d_in, const int* in_sizes, int n_in,
                              void* d_out, int out_size) {
    const float* query = (const float*)d_in[0];
    const float* key   = (const float*)d_in[1];
    const float* value = (const float*)d_in[2];
    const float* wq    = (const float*)d_in[3];
    const float* wk    = (const float*)d_in[4];
    const float* wv    = (const float*)d_in[5];
    float* out = (float*)d_out;

    k_qproj  <<<dim3(4, BB), 256>>>(query, wq);
    k_uproj  <<<dim3(8, BB), 128>>>(wk);
    k_scores <<<dim3(16, BB), 256>>>(key);
    k_softmax<<<BB * HH, 256>>>();
    k_wpart  <<<dim3(4, 4, BB), 256>>>(value);
    k_wsum   <<<512, 256>>>();
    k_oproj  <<<dim3(4, BB), 256>>>(wv, out);
}

// round 2
// speedup vs baseline: 1.1292x; 1.1292x over previous
#include <cuda_runtime.h>

#define BB 32
#define NN 4096
#define DD 1024
#define HH 16

// Scratch (device globals)
__device__ float g_q[BB * DD];             // q projection  [B][H*64]
__device__ float g_Ut[BB * DD * HH];       // folded key vectors, TRANSPOSED: [b][d][h] (scaled 1/8)
__device__ float g_att[BB * HH * NN];      // scores -> attn (softmaxed in place)
__device__ float g_wp[8][BB * HH * DD];    // partial attn@value over 8 n-segments
__device__ float g_w[BB * HH * DD];        // summed attn@value

typedef unsigned long long u64;

__device__ __forceinline__ void fma2(u64 &d, u64 a, u64 b) {
    asm("fma.rn.f32x2 %0, %1, %2, %0;" : "+l"(d) : "l"(a), "l"(b));
}
__device__ __forceinline__ u64 pack2(float lo, float hi) {
    u64 r; asm("mov.b64 %0, {%1, %2};" : "=l"(r) : "f"(lo), "f"(hi)); return r;
}
__device__ __forceinline__ void unpack2(u64 v, float &lo, float &hi) {
    asm("mov.b64 {%0, %1}, %2;" : "=f"(lo), "=f"(hi) : "l"(v));
}
__device__ __forceinline__ unsigned smem_u32(const void* p) {
    return (unsigned)__cvta_generic_to_shared(p);
}
__device__ __forceinline__ void cpasync16(unsigned dst, const void* src) {
    asm volatile("cp.async.cg.shared.global [%0], [%1], 16;\n" :: "r"(dst), "l"(src));
}
#define CP_COMMIT() asm volatile("cp.async.commit_group;\n" ::: "memory")
#define CP_WAIT(n)  asm volatile("cp.async.wait_group %0;\n" :: "n"(n) : "memory")

// ---------------------------------------------------------------------------
// Kernel A: q[b,c] = sum_d query[b,d] * wq[d,c].  Block: (c-tile 128, b-group 4).
// ---------------------------------------------------------------------------
__global__ __launch_bounds__(128) void k_qproj(const float* __restrict__ query,
                                               const float* __restrict__ wq) {
    const int tx = threadIdx.x;
    const int c0 = blockIdx.x * 128;
    const int b0 = blockIdx.y * 4;
    __shared__ __align__(16) float sq[4][DD];   // 16KB

#pragma unroll
    for (int i = 0; i < 8; i++) {
        int fl = i * 128 + tx;        // 1024 float4 total
        int bb = fl >> 8;
        int d4 = fl & 255;
        *(float4*)&sq[bb][d4 * 4] =
            *(const float4*)(query + (size_t)(b0 + bb) * DD + d4 * 4);
    }
    __syncthreads();

    u64 acc[4] = {0ull, 0ull, 0ull, 0ull};
    const float* wc = wq + c0 + tx;
#pragma unroll 8
    for (int d = 0; d < DD; d += 2) {
        float w0 = wc[(size_t)d * DD];
        float w1 = wc[(size_t)(d + 1) * DD];
        u64 w2 = pack2(w0, w1);
#pragma unroll
        for (int bb = 0; bb < 4; bb++) {
            u64 q2 = *(const u64*)&sq[bb][d];     // (q[d], q[d+1]) broadcast
            fma2(acc[bb], q2, w2);
        }
    }
#pragma unroll
    for (int bb = 0; bb < 4; bb++) {
        float lo, hi; unpack2(acc[bb], lo, hi);
        g_q[(size_t)(b0 + bb) * DD + c0 + tx] = lo + hi;
    }
}

// ---------------------------------------------------------------------------
// Kernel B: Ut[b,d,h] = (1/8) * sum_{c<64} wk[d, h*64+c] * q[b, h*64+c]
// Block = (d-tile 128, h). wk tile read exactly once; one barrier; all 32 b.
// ---------------------------------------------------------------------------
__global__ __launch_bounds__(128) void k_uproj(const float* __restrict__ wk) {
    const int tx = threadIdx.x;
    const int d0 = blockIdx.x * 128;
    const int h  = blockIdx.y;
    __shared__ __align__(16) float4 swk4[128 * 17];  // row stride 17 float4 (16+1 pad)
    __shared__ __align__(16) float  sq[32][64];      // 8KB

#pragma unroll
    for (int i = 0; i < 16; i++) {
        int fl = i * 128 + tx;
        int r  = fl >> 4;
        int c4 = fl & 15;
        swk4[r * 17 + c4] =
            *(const float4*)(wk + (size_t)(d0 + r) * DD + h * 64 + c4 * 4);
    }
#pragma unroll
    for (int i = 0; i < 4; i++) {
        int fl = i * 128 + tx;
        int bb = fl >> 4;
        int c4 = fl & 15;
        *(float4*)&sq[bb][c4 * 4] =
            *(const float4*)(g_q + (size_t)bb * DD + h * 64 + c4 * 4);
    }
    __syncthreads();

    const int dst_base = (d0 + tx) * HH + h;
#pragma unroll 1
    for (int bb = 0; bb < 32; bb++) {
        u64 a2 = 0ull;
#pragma unroll
        for (int c4 = 0; c4 < 16; c4++) {
            ulonglong2 w2 = *(const ulonglong2*)&swk4[tx * 17 + c4];
            ulonglong2 q2 = *(const ulonglong2*)&sq[bb][c4 * 4];
            fma2(a2, w2.x, q2.x);
            fma2(a2, w2.y, q2.y);
        }
        float lo, hi; unpack2(a2, lo, hi);
        g_Ut[(size_t)bb * (DD * HH) + dst_base] = (lo + hi) * 0.125f;
    }
}

// ---------------------------------------------------------------------------
// Kernel C: scores[b,h,n] = sum_d key[b,n,d] * Ut[b,d,h]   (streams key 512MB)
// Block (n-tile 128, b), 128 threads; 2-stage cp.async double buffer.
// ---------------------------------------------------------------------------
__global__ __launch_bounds__(128) void k_scores(const float* __restrict__ key) {
    const int tx = threadIdx.x;
    const int b  = blockIdx.y;
    const int n0 = blockIdx.x * 128;

    __shared__ __align__(16) float4 sk4[2][128 * 9];  // [n][8 data + 1 pad] float4
    __shared__ __align__(16) float4 sU4[2][128];      // 32dd x 16h floats

    const float* keyb = key + ((size_t)b * NN + n0) * DD;
    const float* Utbb = g_Ut + (size_t)b * (DD * HH);

    u64 acc[8];
#pragma unroll
    for (int p = 0; p < 8; p++) acc[p] = 0ull;

    // issue chunk 0
    {
#pragma unroll
        for (int it = 0; it < 8; it++) {
            int fl = it * 128 + tx;
            int n = fl >> 3, q4 = fl & 7;
            cpasync16(smem_u32(&sk4[0][n * 9 + q4]),
                      keyb + (size_t)n * DD + q4 * 4);
        }
        cpasync16(smem_u32(&sU4[0][tx]), Utbb + tx * 4);
        CP_COMMIT();
    }

#pragma unroll 1
    for (int ch = 0; ch < 32; ch++) {
        if (ch + 1 < 32) {
            const int st = (ch + 1) & 1, d0 = (ch + 1) * 32;
#pragma unroll
            for (int it = 0; it < 8; it++) {
                int fl = it * 128 + tx;
                int n = fl >> 3, q4 = fl & 7;
                cpasync16(smem_u32(&sk4[st][n * 9 + q4]),
                          keyb + (size_t)n * DD + d0 + q4 * 4);
            }
            cpasync16(smem_u32(&sU4[st][tx]), Utbb + d0 * HH + tx * 4);
            CP_COMMIT();
            CP_WAIT(1);
        } else {
            CP_WAIT(0);
        }
        __syncthreads();

        const int st = ch & 1;
#pragma unroll
        for (int g = 0; g < 8; g++) {
            float4 kv4 = sk4[st][tx * 9 + g];
            float kvs[4] = {kv4.x, kv4.y, kv4.z, kv4.w};
#pragma unroll
            for (int s = 0; s < 4; s++) {
                int dd = g * 4 + s;
                u64 kv2 = pack2(kvs[s], kvs[s]);
                const ulonglong2* uv = (const ulonglong2*)&sU4[st][dd * 4];
                ulonglong2 u0 = uv[0], u1 = uv[1];
                fma2(acc[0], u0.x, kv2);
                fma2(acc[1], u0.y, kv2);
                fma2(acc[2], u1.x, kv2);
                fma2(acc[3], u1.y, kv2);
                ulonglong2 u2 = uv[2], u3 = uv[3];
                fma2(acc[4], u2.x, kv2);
                fma2(acc[5], u2.y, kv2);
                fma2(acc[6], u3.x, kv2);
                fma2(acc[7], u3.y, kv2);
            }
        }
        __syncthreads();
    }

#pragma unroll
    for (int p = 0; p < 8; p++) {
        float lo, hi; unpack2(acc[p], lo, hi);
        g_att[((size_t)b * HH + 2 * p)     * NN + n0 + tx] = lo;
        g_att[((size_t)b * HH + 2 * p + 1) * NN + n0 + tx] = hi;
    }
}

// ---------------------------------------------------------------------------
// Kernel D: in-place softmax over N per (b,h) row.
// ---------------------------------------------------------------------------
__global__ __launch_bounds__(256) void k_softmax() {
    int row = blockIdx.x;
    int tx  = threadIdx.x;
    float4* pv = reinterpret_cast<float4*>(g_att + (size_t)row * NN);

    float4 x[4];
#pragma unroll
    for (int i = 0; i < 4; i++) x[i] = pv[i * 256 + tx];

    float m = -3e38f;
#pragma unroll
    for (int i = 0; i < 4; i++)
        m = fmaxf(m, fmaxf(fmaxf(x[i].x, x[i].y), fmaxf(x[i].z, x[i].w)));
    __shared__ float r1[8], r2[8];
#pragma unroll
    for (int o = 16; o; o >>= 1) m = fmaxf(m, __shfl_xor_sync(0xffffffffu, m, o));
    if ((tx & 31) == 0) r1[tx >> 5] = m;
    __syncthreads();
    float bm = r1[0];
#pragma unroll
    for (int w = 1; w < 8; w++) bm = fmaxf(bm, r1[w]);

    float s = 0.f;
#pragma unroll
    for (int i = 0; i < 4; i++) {
        x[i].x = __expf(x[i].x - bm);
        x[i].y = __expf(x[i].y - bm);
        x[i].z = __expf(x[i].z - bm);
        x[i].w = __expf(x[i].w - bm);
        s += x[i].x + x[i].y + x[i].z + x[i].w;
    }
#pragma unroll
    for (int o = 16; o; o >>= 1) s += __shfl_xor_sync(0xffffffffu, s, o);
    if ((tx & 31) == 0) r2[tx >> 5] = s;
    __syncthreads();
    float tot = 0.f;
#pragma unroll
    for (int w = 0; w < 8; w++) tot += r2[w];
    float inv = 1.f / tot;
#pragma unroll
    for (int i = 0; i < 4; i++) {
        x[i].x *= inv; x[i].y *= inv; x[i].z *= inv; x[i].w *= inv;
        pv[i * 256 + tx] = x[i];
    }
}

// ---------------------------------------------------------------------------
// Kernel E: wp[seg][b,h,d] = sum_{n in seg(512)} attn[b,h,n] * value[b,n,d]
// ---------------------------------------------------------------------------
__global__ __launch_bounds__(256) void k_wpart(const float* __restrict__ value) {
    const int tx  = threadIdx.x;
    const int d0  = blockIdx.x * 256;
    const int seg = blockIdx.y;
    const int b   = blockIdx.z;

    __shared__ __align__(16) float sA[512 * 20];   // [n][16h + 4 pad], 40KB

    const float* attb = g_att + (size_t)b * HH * NN + seg * 512;
#pragma unroll
    for (int i = 0; i < 32; i++) {
        int fl = i * 256 + tx;
        int h = fl >> 9, n = fl & 511;
        sA[n * 20 + h] = attb[(size_t)h * NN + n];
    }
    __syncthreads();

    u64 acc[8];
#pragma unroll
    for (int p = 0; p < 8; p++) acc[p] = 0ull;

    const float* valb = value + ((size_t)b * NN + seg * 512) * DD + d0 + tx;

    float vv[8], vn[8];
#pragma unroll
    for (int j = 0; j < 8; j++) vv[j] = __ldcs(valb + (size_t)j * DD);

#pragma unroll 1
    for (int n = 0; n < 512; n += 8) {
        if (n + 8 < 512) {
#pragma unroll
            for (int j = 0; j < 8; j++)
                vn[j] = __ldcs(valb + (size_t)(n + 8 + j) * DD);
        }
#pragma unroll
        for (int j = 0; j < 8; j++) {
            u64 v2 = pack2(vv[j], vv[j]);
            const ulonglong2* av = (const ulonglong2*)&sA[(n + j) * 20];
            ulonglong2 a0 = av[0], a1 = av[1];
            fma2(acc[0], a0.x, v2);
            fma2(acc[1], a0.y, v2);
            fma2(acc[2], a1.x, v2);
            fma2(acc[3], a1.y, v2);
            ulonglong2 a2 = av[2], a3 = av[3];
            fma2(acc[4], a2.x, v2);
            fma2(acc[5], a2.y, v2);
            fma2(acc[6], a3.x, v2);
            fma2(acc[7], a3.y, v2);
        }
#pragma unroll
        for (int j = 0; j < 8; j++) vv[j] = vn[j];
    }

#pragma unroll
    for (int p = 0; p < 8; p++) {
        float lo, hi; unpack2(acc[p], lo, hi);
        g_wp[seg][((size_t)b * HH + 2 * p)     * DD + d0 + tx] = lo;
        g_wp[seg][((size_t)b * HH + 2 * p + 1) * DD + d0 + tx] = hi;
    }
}

// ---------------------------------------------------------------------------
// Kernel G: g_w = sum over 8 segment partials
// ---------------------------------------------------------------------------
__global__ __launch_bounds__(256) void k_wsum() {
    int i = blockIdx.x * 256 + threadIdx.x;
    float4 o = reinterpret_cast<float4*>(g_wp[0])[i];
#pragma unroll
    for (int p = 1; p < 8; p++) {
        float4 a = reinterpret_cast<float4*>(g_wp[p])[i];
        o.x += a.x; o.y += a.y; o.z += a.z; o.w += a.w;
    }
    reinterpret_cast<float4*>(g_w)[i] = o;
}

// ---------------------------------------------------------------------------
// Kernel F: out[b,c] = sum_d w[b, c>>6, d] * wv[d, c]
// ---------------------------------------------------------------------------
__global__ __launch_bounds__(128) void k_oproj(const float* __restrict__ wv,
                                               float* __restrict__ out) {
    const int tx = threadIdx.x;
    const int c0 = blockIdx.x * 128;
    const int b0 = blockIdx.y * 4;
    const int h0 = c0 >> 6;
    __shared__ __align__(16) float sw[4][2 * DD];   // 32KB

#pragma unroll
    for (int i = 0; i < 16; i++) {
        int fl = i * 128 + tx;
        int bb = fl >> 9;
        int d4 = fl & 511;
        *(float4*)&sw[bb][d4 * 4] =
            *(const float4*)(g_w + ((size_t)(b0 + bb) * HH + h0) * DD + d4 * 4);
    }
    __syncthreads();

    const int hin = (tx >> 6);
    u64 acc[4] = {0ull, 0ull, 0ull, 0ull};
    const float* wc = wv + c0 + tx;
#pragma unroll 4
    for (int d = 0; d < DD; d += 2) {
        float w0 = wc[(size_t)d * DD];
        float w1 = wc[(size_t)(d + 1) * DD];
        u64 w2 = pack2(w0, w1);
#pragma unroll
        for (int bb = 0; bb < 4; bb++) {
            u64 s2 = *(const u64*)&sw[bb][hin * DD + d];
            fma2(acc[bb], s2, w2);
        }
    }
#pragma unroll
    for (int bb = 0; bb < 4; bb++) {
        float lo, hi; unpack2(acc[bb], lo, hi);
        out[(size_t)(b0 + bb) * DD + c0 + tx] = lo + hi;
    }
}

// ---------------------------------------------------------------------------
extern "C" void kernel_launch(void* const* d_in, const int* in_sizes, int n_in,
                              void* d_out, int out_size) {
    const float* query = (const float*)d_in[0];
    const float* key   = (const float*)d_in[1];
    const float* value = (const float*)d_in[2];
    const float* wq    = (const float*)d_in[3];
    const float* wk    = (const float*)d_in[4];
    const float* wv    = (const float*)d_in[5];
    float* out = (float*)d_out;

    k_qproj  <<<dim3(8, 8),     128>>>(query, wq);
    k_uproj  <<<dim3(8, HH),    128>>>(wk);
    k_scores <<<dim3(32, BB),   128>>>(key);
    k_softmax<<<BB * HH,        256>>>();
    k_wpart  <<<dim3(4, 8, BB), 256>>>(value);
    k_wsum   <<<512,            256>>>();
    k_oproj  <<<dim3(8, 8),     128>>>(wv, out);
}

// round 3
// speedup vs baseline: 1.4555x; 1.2889x over previous
#include <cuda_runtime.h>

#define BB 32
#define NN 4096
#define DD 1024
#define HH 16

// Scratch (device globals)
__device__ float g_qp[4][BB * DD];         // q projection partials over 4 d-ranges
__device__ float g_Ut[BB * DD * HH];       // folded key vectors, transposed [b][d][h] (scaled 1/8)
__device__ float g_att[BB * HH * NN];      // scores -> attn (softmaxed in place)
__device__ float g_wp[8][BB * HH * DD];    // partial attn@value over 8 n-segments

typedef unsigned long long u64;

__device__ __forceinline__ void fma2(u64 &d, u64 a, u64 b) {
    asm("fma.rn.f32x2 %0, %1, %2, %0;" : "+l"(d) : "l"(a), "l"(b));
}
__device__ __forceinline__ u64 pack2(float lo, float hi) {
    u64 r; asm("mov.b64 %0, {%1, %2};" : "=l"(r) : "f"(lo), "f"(hi)); return r;
}
__device__ __forceinline__ void unpack2(u64 v, float &lo, float &hi) {
    asm("mov.b64 {%0, %1}, %2;" : "=f"(lo), "=f"(hi) : "l"(v));
}
__device__ __forceinline__ unsigned smem_u32(const void* p) {
    return (unsigned)__cvta_generic_to_shared(p);
}
__device__ __forceinline__ void cpasync16(unsigned dst, const void* src) {
    asm volatile("cp.async.cg.shared.global [%0], [%1], 16;\n" :: "r"(dst), "l"(src));
}
#define CP_COMMIT() asm volatile("cp.async.commit_group;\n" ::: "memory")
#define CP_WAIT(n)  asm volatile("cp.async.wait_group %0;\n" :: "n"(n) : "memory")

// ---------------------------------------------------------------------------
// Kernel A: qp[dsp][b,c] = sum_{d in dsp-range(256)} query[b,d] * wq[d,c]
// grid (8 c-tiles, 8 b-groups, 4 d-splits) = 256 blocks, 128 thr.
// Also zero-initializes d_out (for oproj's atomicAdd).
// ---------------------------------------------------------------------------
__global__ __launch_bounds__(128) void k_qproj(const float* __restrict__ query,
                                               const float* __restrict__ wq,
                                               float* __restrict__ out) {
    const int tx  = threadIdx.x;
    const int c0  = blockIdx.x * 128;
    const int b0  = blockIdx.y * 4;
    const int dsp = blockIdx.z;
    const int dr0 = dsp * 256;

    // zero d_out: 256 blocks x 128 threads covers 32768 floats exactly
    {
        int lin = blockIdx.x + 8 * blockIdx.y + 64 * blockIdx.z;
        out[lin * 128 + tx] = 0.0f;
    }

    __shared__ __align__(16) float sq[4][256];   // 4KB
#pragma unroll
    for (int i = 0; i < 2; i++) {
        int fl = i * 128 + tx;              // 256 float4
        int bb = fl >> 6, d4 = fl & 63;
        *(float4*)&sq[bb][d4 * 4] =
            *(const float4*)(query + (size_t)(b0 + bb) * DD + dr0 + d4 * 4);
    }
    __syncthreads();

    u64 acc[4] = {0ull, 0ull, 0ull, 0ull};
    const float* wc = wq + (size_t)dr0 * DD + c0 + tx;
#pragma unroll 8
    for (int d = 0; d < 256; d += 2) {
        float w0 = wc[(size_t)d * DD];
        float w1 = wc[(size_t)(d + 1) * DD];
        u64 w2 = pack2(w0, w1);
#pragma unroll
        for (int bb = 0; bb < 4; bb++) {
            u64 q2 = *(const u64*)&sq[bb][d];
            fma2(acc[bb], q2, w2);
        }
    }
#pragma unroll
    for (int bb = 0; bb < 4; bb++) {
        float lo, hi; unpack2(acc[bb], lo, hi);
        g_qp[dsp][(size_t)(b0 + bb) * DD + c0 + tx] = lo + hi;
    }
}

// ---------------------------------------------------------------------------
// Kernel B: Ut[b,d,h] = (1/8) * sum_{c<64} wk[d, h*64+c] * q[b, h*64+c]
// grid (8 d-tiles, 16 h), 128 thr. wk tile staged once then HOISTED to regs.
// q partials (4) summed during staging.
// ---------------------------------------------------------------------------
__global__ __launch_bounds__(128) void k_uproj(const float* __restrict__ wk) {
    const int tx = threadIdx.x;
    const int d0 = blockIdx.x * 128;
    const int h  = blockIdx.y;
    __shared__ __align__(16) float4 swk4[128 * 17];  // 34.8KB
    __shared__ __align__(16) float  sq[32][64];      // 8KB

#pragma unroll
    for (int i = 0; i < 16; i++) {
        int fl = i * 128 + tx;
        int r  = fl >> 4, c4 = fl & 15;
        swk4[r * 17 + c4] =
            *(const float4*)(wk + (size_t)(d0 + r) * DD + h * 64 + c4 * 4);
    }
#pragma unroll
    for (int i = 0; i < 4; i++) {
        int fl = i * 128 + tx;
        int bb = fl >> 4, c4 = fl & 15;
        float4 s = *(const float4*)(g_qp[0] + (size_t)bb * DD + h * 64 + c4 * 4);
#pragma unroll
        for (int p = 1; p < 4; p++) {
            float4 a = *(const float4*)(g_qp[p] + (size_t)bb * DD + h * 64 + c4 * 4);
            s.x += a.x; s.y += a.y; s.z += a.z; s.w += a.w;
        }
        *(float4*)&sq[bb][c4 * 4] = s;
    }
    __syncthreads();

    // hoist this thread's wk row into registers (16 ulonglong2 = 64 regs)
    ulonglong2 wreg[16];
#pragma unroll
    for (int c4 = 0; c4 < 16; c4++)
        wreg[c4] = *(const ulonglong2*)&swk4[tx * 17 + c4];

    const int dst_base = (d0 + tx) * HH + h;
#pragma unroll 2
    for (int bb = 0; bb < 32; bb++) {
        u64 a2 = 0ull;
#pragma unroll
        for (int c4 = 0; c4 < 16; c4++) {
            ulonglong2 q2 = *(const ulonglong2*)&sq[bb][c4 * 4];
            fma2(a2, wreg[c4].x, q2.x);
            fma2(a2, wreg[c4].y, q2.y);
        }
        float lo, hi; unpack2(a2, lo, hi);
        g_Ut[(size_t)bb * (DD * HH) + dst_base] = (lo + hi) * 0.125f;
    }
}

// ---------------------------------------------------------------------------
// Kernel C: scores[b,h,n] = sum_d key[b,n,d] * Ut[b,d,h]   (streams key 512MB)
// grid (16 n-tiles of 256, 32 b), 128 thr; thread owns n and n+128.
// d-chunk 16, 2-stage cp.async. smem 43KB -> ~5 CTAs/SM, fully resident grid.
// ---------------------------------------------------------------------------
__global__ __launch_bounds__(128) void k_scores(const float* __restrict__ key) {
    const int tx = threadIdx.x;
    const int b  = blockIdx.y;
    const int n0 = blockIdx.x * 256;

    __shared__ __align__(16) float4 sk4[2][256 * 5];  // [n][4 data + 1 pad] f4 = 40KB
    __shared__ __align__(16) float4 sU4[2][64];       // 16d x 16h floats = 2KB

    const float* keyb = key + ((size_t)b * NN + n0) * DD;
    const float* Utbb = g_Ut + (size_t)b * (DD * HH);

    u64 acc_a[8], acc_b[8];
#pragma unroll
    for (int p = 0; p < 8; p++) { acc_a[p] = 0ull; acc_b[p] = 0ull; }

    // prologue: issue chunk 0
    {
#pragma unroll
        for (int it = 0; it < 8; it++) {
            int fl = it * 128 + tx;
            int n = fl >> 2, q4 = fl & 3;
            cpasync16(smem_u32(&sk4[0][n * 5 + q4]), keyb + (size_t)n * DD + q4 * 4);
        }
        if (tx < 64) cpasync16(smem_u32(&sU4[0][tx]), Utbb + tx * 4);
        CP_COMMIT();
    }

#pragma unroll 1
    for (int ch = 0; ch < 64; ch++) {
        if (ch + 1 < 64) {
            const int st = (ch + 1) & 1, d0 = (ch + 1) * 16;
#pragma unroll
            for (int it = 0; it < 8; it++) {
                int fl = it * 128 + tx;
                int n = fl >> 2, q4 = fl & 3;
                cpasync16(smem_u32(&sk4[st][n * 5 + q4]),
                          keyb + (size_t)n * DD + d0 + q4 * 4);
            }
            if (tx < 64) cpasync16(smem_u32(&sU4[st][tx]), Utbb + d0 * HH + tx * 4);
            CP_COMMIT();
            CP_WAIT(1);
        } else {
            CP_WAIT(0);
        }
        __syncthreads();

        const int st = ch & 1;
        float4 ka[4], kb[4];
#pragma unroll
        for (int g = 0; g < 4; g++) {
            ka[g] = sk4[st][tx * 5 + g];
            kb[g] = sk4[st][(tx + 128) * 5 + g];
        }
        const float* Uf = (const float*)sU4[st];
#pragma unroll
        for (int g = 0; g < 4; g++) {
            float kas[4] = {ka[g].x, ka[g].y, ka[g].z, ka[g].w};
            float kbs[4] = {kb[g].x, kb[g].y, kb[g].z, kb[g].w};
#pragma unroll
            for (int s = 0; s < 4; s++) {
                int dd = g * 4 + s;
                u64 kva = pack2(kas[s], kas[s]);
                u64 kvb = pack2(kbs[s], kbs[s]);
                const ulonglong2* uv = (const ulonglong2*)&Uf[dd * 16];
                ulonglong2 u0 = uv[0], u1 = uv[1];
                fma2(acc_a[0], u0.x, kva);  fma2(acc_b[0], u0.x, kvb);
                fma2(acc_a[1], u0.y, kva);  fma2(acc_b[1], u0.y, kvb);
                fma2(acc_a[2], u1.x, kva);  fma2(acc_b[2], u1.x, kvb);
                fma2(acc_a[3], u1.y, kva);  fma2(acc_b[3], u1.y, kvb);
                ulonglong2 u2 = uv[2], u3 = uv[3];
                fma2(acc_a[4], u2.x, kva);  fma2(acc_b[4], u2.x, kvb);
                fma2(acc_a[5], u2.y, kva);  fma2(acc_b[5], u2.y, kvb);
                fma2(acc_a[6], u3.x, kva);  fma2(acc_b[6], u3.x, kvb);
                fma2(acc_a[7], u3.y, kva);  fma2(acc_b[7], u3.y, kvb);
            }
        }
        __syncthreads();
    }

#pragma unroll
    for (int p = 0; p < 8; p++) {
        float lo, hi;
        unpack2(acc_a[p], lo, hi);
        g_att[((size_t)b * HH + 2 * p)     * NN + n0 + tx] = lo;
        g_att[((size_t)b * HH + 2 * p + 1) * NN + n0 + tx] = hi;
        unpack2(acc_b[p], lo, hi);
        g_att[((size_t)b * HH + 2 * p)     * NN + n0 + 128 + tx] = lo;
        g_att[((size_t)b * HH + 2 * p + 1) * NN + n0 + 128 + tx] = hi;
    }
}

// ---------------------------------------------------------------------------
// Kernel D: in-place softmax over N per (b,h) row.
// ---------------------------------------------------------------------------
__global__ __launch_bounds__(256) void k_softmax() {
    int row = blockIdx.x;
    int tx  = threadIdx.x;
    float4* pv = reinterpret_cast<float4*>(g_att + (size_t)row * NN);

    float4 x[4];
#pragma unroll
    for (int i = 0; i < 4; i++) x[i] = pv[i * 256 + tx];

    float m = -3e38f;
#pragma unroll
    for (int i = 0; i < 4; i++)
        m = fmaxf(m, fmaxf(fmaxf(x[i].x, x[i].y), fmaxf(x[i].z, x[i].w)));
    __shared__ float r1[8], r2[8];
#pragma unroll
    for (int o = 16; o; o >>= 1) m = fmaxf(m, __shfl_xor_sync(0xffffffffu, m, o));
    if ((tx & 31) == 0) r1[tx >> 5] = m;
    __syncthreads();
    float bm = r1[0];
#pragma unroll
    for (int w = 1; w < 8; w++) bm = fmaxf(bm, r1[w]);

    float s = 0.f;
#pragma unroll
    for (int i = 0; i < 4; i++) {
        x[i].x = __expf(x[i].x - bm);
        x[i].y = __expf(x[i].y - bm);
        x[i].z = __expf(x[i].z - bm);
        x[i].w = __expf(x[i].w - bm);
        s += x[i].x + x[i].y + x[i].z + x[i].w;
    }
#pragma unroll
    for (int o = 16; o; o >>= 1) s += __shfl_xor_sync(0xffffffffu, s, o);
    if ((tx & 31) == 0) r2[tx >> 5] = s;
    __syncthreads();
    float tot = 0.f;
#pragma unroll
    for (int w = 0; w < 8; w++) tot += r2[w];
    float inv = 1.f / tot;
#pragma unroll
    for (int i = 0; i < 4; i++) {
        x[i].x *= inv; x[i].y *= inv; x[i].z *= inv; x[i].w *= inv;
        pv[i * 256 + tx] = x[i];
    }
}

// ---------------------------------------------------------------------------
// Kernel E: wp[seg][b,h,d] = sum_{n in seg(512)} attn[b,h,n] * value[b,n,d]
// grid (2 d-tiles of 512, 8 seg, 32 b), 256 thr; thread owns d and d+256.
// att slab staged once; barrier-free mainloop with 4-deep x2 load pipeline.
// ---------------------------------------------------------------------------
__global__ __launch_bounds__(256) void k_wpart(const float* __restrict__ value) {
    const int tx  = threadIdx.x;
    const int d0  = blockIdx.x * 512;
    const int seg = blockIdx.y;
    const int b   = blockIdx.z;

    __shared__ __align__(16) float sA[512 * 20];   // [n][16h + 4 pad], 40KB

    const float* attb = g_att + (size_t)b * HH * NN + seg * 512;
#pragma unroll
    for (int i = 0; i < 32; i++) {
        int fl = i * 256 + tx;
        int h = fl >> 9, n = fl & 511;
        sA[n * 20 + h] = attb[(size_t)h * NN + n];
    }
    __syncthreads();

    u64 acc1[8], acc2[8];
#pragma unroll
    for (int p = 0; p < 8; p++) { acc1[p] = 0ull; acc2[p] = 0ull; }

    const float* v1 = value + ((size_t)b * NN + seg * 512) * DD + d0 + tx;
    const float* v2 = v1 + 256;

    float va[4], vb[4], na[4], nb[4];
#pragma unroll
    for (int j = 0; j < 4; j++) {
        va[j] = __ldcs(v1 + (size_t)j * DD);
        vb[j] = __ldcs(v2 + (size_t)j * DD);
    }

#pragma unroll 1
    for (int n = 0; n < 512; n += 4) {
        if (n + 4 < 512) {
#pragma unroll
            for (int j = 0; j < 4; j++) {
                na[j] = __ldcs(v1 + (size_t)(n + 4 + j) * DD);
                nb[j] = __ldcs(v2 + (size_t)(n + 4 + j) * DD);
            }
        }
#pragma unroll
        for (int j = 0; j < 4; j++) {
            u64 p1 = pack2(va[j], va[j]);
            u64 p2 = pack2(vb[j], vb[j]);
            const ulonglong2* av = (const ulonglong2*)&sA[(n + j) * 20];
            ulonglong2 a0 = av[0], a1 = av[1];
            fma2(acc1[0], a0.x, p1);  fma2(acc2[0], a0.x, p2);
            fma2(acc1[1], a0.y, p1);  fma2(acc2[1], a0.y, p2);
            fma2(acc1[2], a1.x, p1);  fma2(acc2[2], a1.x, p2);
            fma2(acc1[3], a1.y, p1);  fma2(acc2[3], a1.y, p2);
            ulonglong2 a2 = av[2], a3 = av[3];
            fma2(acc1[4], a2.x, p1);  fma2(acc2[4], a2.x, p2);
            fma2(acc1[5], a2.y, p1);  fma2(acc2[5], a2.y, p2);
            fma2(acc1[6], a3.x, p1);  fma2(acc2[6], a3.x, p2);
            fma2(acc1[7], a3.y, p1);  fma2(acc2[7], a3.y, p2);
        }
#pragma unroll
        for (int j = 0; j < 4; j++) { va[j] = na[j]; vb[j] = nb[j]; }
    }

#pragma unroll
    for (int p = 0; p < 8; p++) {
        float lo, hi;
        unpack2(acc1[p], lo, hi);
        g_wp[seg][((size_t)b * HH + 2 * p)     * DD + d0 + tx] = lo;
        g_wp[seg][((size_t)b * HH + 2 * p + 1) * DD + d0 + tx] = hi;
        unpack2(acc2[p], lo, hi);
        g_wp[seg][((size_t)b * HH + 2 * p)     * DD + d0 + 256 + tx] = lo;
        g_wp[seg][((size_t)b * HH + 2 * p + 1) * DD + d0 + 256 + tx] = hi;
    }
}

// ---------------------------------------------------------------------------
// Kernel F: out[b,c] += sum_{d in dsp-range(256)} w[b, c>>6, d] * wv[d, c]
// grid (8 c-tiles, 8 b-groups, 4 d-splits) = 256 blocks, 128 thr.
// Sums the 8 wpart partials during staging; REDG atomicAdd into zeroed d_out.
// ---------------------------------------------------------------------------
__global__ __launch_bounds__(128) void k_oproj(const float* __restrict__ wv,
                                               float* __restrict__ out) {
    const int tx  = threadIdx.x;
    const int c0  = blockIdx.x * 128;
    const int b0  = blockIdx.y * 4;
    const int dsp = blockIdx.z;
    const int dr0 = dsp * 256;
    const int h0  = c0 >> 6;                    // 2 heads in this c-tile
    __shared__ __align__(16) float sw[4][2][256];   // 8KB

#pragma unroll
    for (int i = 0; i < 4; i++) {
        int fl = i * 128 + tx;                  // 512 float4
        int bb = fl >> 7, hh = (fl >> 6) & 1, d4 = fl & 63;
        size_t gidx = ((size_t)(b0 + bb) * HH + h0 + hh) * DD + dr0 + d4 * 4;
        float4 s = *(const float4*)(g_wp[0] + gidx);
#pragma unroll
        for (int p = 1; p < 8; p++) {
            float4 a = *(const float4*)(g_wp[p] + gidx);
            s.x += a.x; s.y += a.y; s.z += a.z; s.w += a.w;
        }
        *(float4*)&sw[bb][hh][d4 * 4] = s;
    }
    __syncthreads();

    const int hin = tx >> 6;
    u64 acc[4] = {0ull, 0ull, 0ull, 0ull};
    const float* wc = wv + (size_t)dr0 * DD + c0 + tx;
#pragma unroll 8
    for (int d = 0; d < 256; d += 2) {
        float w0 = wc[(size_t)d * DD];
        float w1 = wc[(size_t)(d + 1) * DD];
        u64 w2 = pack2(w0, w1);
#pragma unroll
        for (int bb = 0; bb < 4; bb++) {
            u64 s2 = *(const u64*)&sw[bb][hin][d];
            fma2(acc[bb], s2, w2);
        }
    }
#pragma unroll
    for (int bb = 0; bb < 4; bb++) {
        float lo, hi; unpack2(acc[bb], lo, hi);
        atomicAdd(&out[(size_t)(b0 + bb) * DD + c0 + tx], lo + hi);
    }
}

// ---------------------------------------------------------------------------
extern "C" void kernel_launch(void* const* d_in, const int* in_sizes, int n_in,
                              void* d_out, int out_size) {
    const float* query = (const float*)d_in[0];
    const float* key   = (const float*)d_in[1];
    const float* value = (const float*)d_in[2];
    const float* wq    = (const float*)d_in[3];
    const float* wk    = (const float*)d_in[4];
    const float* wv    = (const float*)d_in[5];
    float* out = (float*)d_out;

    k_qproj  <<<dim3(8, 8, 4),  128>>>(query, wq, out);
    k_uproj  <<<dim3(8, HH),    128>>>(wk);
    k_scores <<<dim3(16, BB),   128>>>(key);
    k_softmax<<<BB * HH,        256>>>();
    k_wpart  <<<dim3(2, 8, BB), 256>>>(value);
    k_oproj  <<<dim3(8, 8, 4),  128>>>(wv, out);
}

// round 4
// speedup vs baseline: 1.4577x; 1.0015x over previous
#include <cuda_runtime.h>

#define BB 32
#define NN 4096
#define DD 1024
#define HH 16

// Scratch (device globals)
__device__ float g_qp[4][BB * DD];         // q projection partials over 4 d-ranges
__device__ float g_Ut[BB * DD * HH];       // folded key vectors, transposed [b][d][h] (scaled 1/8)
__device__ float g_att[BB * HH * NN];      // scores -> attn (softmaxed in place)
__device__ float g_wp[8][BB * HH * DD];    // partial attn@value over 8 n-segments

typedef unsigned long long u64;

__device__ __forceinline__ void fma2(u64 &d, u64 a, u64 b) {
    asm("fma.rn.f32x2 %0, %1, %2, %0;" : "+l"(d) : "l"(a), "l"(b));
}
__device__ __forceinline__ u64 pack2(float lo, float hi) {
    u64 r; asm("mov.b64 %0, {%1, %2};" : "=l"(r) : "f"(lo), "f"(hi)); return r;
}
__device__ __forceinline__ void unpack2(u64 v, float &lo, float &hi) {
    asm("mov.b64 {%0, %1}, %2;" : "=f"(lo), "=f"(hi) : "l"(v));
}
__device__ __forceinline__ unsigned smem_u32(const void* p) {
    return (unsigned)__cvta_generic_to_shared(p);
}
__device__ __forceinline__ void cpasync16(unsigned dst, const void* src) {
    asm volatile("cp.async.cg.shared.global [%0], [%1], 16;\n" :: "r"(dst), "l"(src));
}
#define CP_COMMIT() asm volatile("cp.async.commit_group;\n" ::: "memory")
#define CP_WAIT(n)  asm volatile("cp.async.wait_group %0;\n" :: "n"(n) : "memory")

// ---------------------------------------------------------------------------
// Kernel A: qp[dsp][b,c] = sum_{d in dsp-range(256)} query[b,d] * wq[d,c]
// grid (8 c-tiles, 8 b-groups, 4 d-splits) = 256 blocks, 128 thr.
// Also zero-initializes d_out (for oproj's atomicAdd).
// ---------------------------------------------------------------------------
__global__ __launch_bounds__(128) void k_qproj(const float* __restrict__ query,
                                               const float* __restrict__ wq,
                                               float* __restrict__ out) {
    const int tx  = threadIdx.x;
    const int c0  = blockIdx.x * 128;
    const int b0  = blockIdx.y * 4;
    const int dsp = blockIdx.z;
    const int dr0 = dsp * 256;

    // zero d_out: 256 blocks x 128 threads covers 32768 floats exactly
    {
        int lin = blockIdx.x + 8 * blockIdx.y + 64 * blockIdx.z;
        out[lin * 128 + tx] = 0.0f;
    }

    __shared__ __align__(16) float sq[4][256];   // 4KB
#pragma unroll
    for (int i = 0; i < 2; i++) {
        int fl = i * 128 + tx;              // 256 float4
        int bb = fl >> 6, d4 = fl & 63;
        *(float4*)&sq[bb][d4 * 4] =
            *(const float4*)(query + (size_t)(b0 + bb) * DD + dr0 + d4 * 4);
    }
    __syncthreads();

    u64 acc[4] = {0ull, 0ull, 0ull, 0ull};
    const float* wc = wq + (size_t)dr0 * DD + c0 + tx;
#pragma unroll 8
    for (int d = 0; d < 256; d += 2) {
        float w0 = wc[(size_t)d * DD];
        float w1 = wc[(size_t)(d + 1) * DD];
        u64 w2 = pack2(w0, w1);
#pragma unroll
        for (int bb = 0; bb < 4; bb++) {
            u64 q2 = *(const u64*)&sq[bb][d];
            fma2(acc[bb], q2, w2);
        }
    }
#pragma unroll
    for (int bb = 0; bb < 4; bb++) {
        float lo, hi; unpack2(acc[bb], lo, hi);
        g_qp[dsp][(size_t)(b0 + bb) * DD + c0 + tx] = lo + hi;
    }
}

// ---------------------------------------------------------------------------
// Kernel B: Ut[b,d,h] = (1/8) * sum_{c<64} wk[d, h*64+c] * q[b, h*64+c]
// grid (8 d-tiles, 16 h), 128 thr. wk tile staged once then HOISTED to regs.
// q partials (4) summed during staging.
// ---------------------------------------------------------------------------
__global__ __launch_bounds__(128) void k_uproj(const float* __restrict__ wk) {
    const int tx = threadIdx.x;
    const int d0 = blockIdx.x * 128;
    const int h  = blockIdx.y;
    __shared__ __align__(16) float4 swk4[128 * 17];  // 34.8KB
    __shared__ __align__(16) float  sq[32][64];      // 8KB

#pragma unroll
    for (int i = 0; i < 16; i++) {
        int fl = i * 128 + tx;
        int r  = fl >> 4, c4 = fl & 15;
        swk4[r * 17 + c4] =
            *(const float4*)(wk + (size_t)(d0 + r) * DD + h * 64 + c4 * 4);
    }
#pragma unroll
    for (int i = 0; i < 4; i++) {
        int fl = i * 128 + tx;
        int bb = fl >> 4, c4 = fl & 15;
        float4 s = *(const float4*)(g_qp[0] + (size_t)bb * DD + h * 64 + c4 * 4);
#pragma unroll
        for (int p = 1; p < 4; p++) {
            float4 a = *(const float4*)(g_qp[p] + (size_t)bb * DD + h * 64 + c4 * 4);
            s.x += a.x; s.y += a.y; s.z += a.z; s.w += a.w;
        }
        *(float4*)&sq[bb][c4 * 4] = s;
    }
    __syncthreads();

    // hoist this thread's wk row into registers (16 ulonglong2 = 64 regs)
    ulonglong2 wreg[16];
#pragma unroll
    for (int c4 = 0; c4 < 16; c4++)
        wreg[c4] = *(const ulonglong2*)&swk4[tx * 17 + c4];

    const int dst_base = (d0 + tx) * HH + h;
#pragma unroll 2
    for (int bb = 0; bb < 32; bb++) {
        u64 a2 = 0ull;
#pragma unroll
        for (int c4 = 0; c4 < 16; c4++) {
            ulonglong2 q2 = *(const ulonglong2*)&sq[bb][c4 * 4];
            fma2(a2, wreg[c4].x, q2.x);
            fma2(a2, wreg[c4].y, q2.y);
        }
        float lo, hi; unpack2(a2, lo, hi);
        g_Ut[(size_t)bb * (DD * HH) + dst_base] = (lo + hi) * 0.125f;
    }
}

// ---------------------------------------------------------------------------
// Kernel C: scores[b,h,n] = sum_d key[b,n,d] * Ut[b,d,h]   (streams key 512MB)
// grid (16 n-tiles of 256, 32 b), 128 thr; thread owns n and n+128.
// d-chunk 16, 2-stage cp.async. smem 43KB -> ~5 CTAs/SM, fully resident grid.
// ---------------------------------------------------------------------------
__global__ __launch_bounds__(128) void k_scores(const float* __restrict__ key) {
    const int tx = threadIdx.x;
    const int b  = blockIdx.y;
    const int n0 = blockIdx.x * 256;

    __shared__ __align__(16) float4 sk4[2][256 * 5];  // [n][4 data + 1 pad] f4 = 40KB
    __shared__ __align__(16) float4 sU4[2][64];       // 16d x 16h floats = 2KB

    const float* keyb = key + ((size_t)b * NN + n0) * DD;
    const float* Utbb = g_Ut + (size_t)b * (DD * HH);

    u64 acc_a[8], acc_b[8];
#pragma unroll
    for (int p = 0; p < 8; p++) { acc_a[p] = 0ull; acc_b[p] = 0ull; }

    // prologue: issue chunk 0
    {
#pragma unroll
        for (int it = 0; it < 8; it++) {
            int fl = it * 128 + tx;
            int n = fl >> 2, q4 = fl & 3;
            cpasync16(smem_u32(&sk4[0][n * 5 + q4]), keyb + (size_t)n * DD + q4 * 4);
        }
        if (tx < 64) cpasync16(smem_u32(&sU4[0][tx]), Utbb + tx * 4);
        CP_COMMIT();
    }

#pragma unroll 1
    for (int ch = 0; ch < 64; ch++) {
        if (ch + 1 < 64) {
            const int st = (ch + 1) & 1, d0 = (ch + 1) * 16;
#pragma unroll
            for (int it = 0; it < 8; it++) {
                int fl = it * 128 + tx;
                int n = fl >> 2, q4 = fl & 3;
                cpasync16(smem_u32(&sk4[st][n * 5 + q4]),
                          keyb + (size_t)n * DD + d0 + q4 * 4);
            }
            if (tx < 64) cpasync16(smem_u32(&sU4[st][tx]), Utbb + d0 * HH + tx * 4);
            CP_COMMIT();
            CP_WAIT(1);
        } else {
            CP_WAIT(0);
        }
        __syncthreads();

        const int st = ch & 1;
        float4 ka[4], kb[4];
#pragma unroll
        for (int g = 0; g < 4; g++) {
            ka[g] = sk4[st][tx * 5 + g];
            kb[g] = sk4[st][(tx + 128) * 5 + g];
        }
        const float* Uf = (const float*)sU4[st];
#pragma unroll
        for (int g = 0; g < 4; g++) {
            float kas[4] = {ka[g].x, ka[g].y, ka[g].z, ka[g].w};
            float kbs[4] = {kb[g].x, kb[g].y, kb[g].z, kb[g].w};
#pragma unroll
            for (int s = 0; s < 4; s++) {
                int dd = g * 4 + s;
                u64 kva = pack2(kas[s], kas[s]);
                u64 kvb = pack2(kbs[s], kbs[s]);
                const ulonglong2* uv = (const ulonglong2*)&Uf[dd * 16];
                ulonglong2 u0 = uv[0], u1 = uv[1];
                fma2(acc_a[0], u0.x, kva);  fma2(acc_b[0], u0.x, kvb);
                fma2(acc_a[1], u0.y, kva);  fma2(acc_b[1], u0.y, kvb);
                fma2(acc_a[2], u1.x, kva);  fma2(acc_b[2], u1.x, kvb);
                fma2(acc_a[3], u1.y, kva);  fma2(acc_b[3], u1.y, kvb);
                ulonglong2 u2 = uv[2], u3 = uv[3];
                fma2(acc_a[4], u2.x, kva);  fma2(acc_b[4], u2.x, kvb);
                fma2(acc_a[5], u2.y, kva);  fma2(acc_b[5], u2.y, kvb);
                fma2(acc_a[6], u3.x, kva);  fma2(acc_b[6], u3.x, kvb);
                fma2(acc_a[7], u3.y, kva);  fma2(acc_b[7], u3.y, kvb);
            }
        }
        __syncthreads();
    }

#pragma unroll
    for (int p = 0; p < 8; p++) {
        float lo, hi;
        unpack2(acc_a[p], lo, hi);
        g_att[((size_t)b * HH + 2 * p)     * NN + n0 + tx] = lo;
        g_att[((size_t)b * HH + 2 * p + 1) * NN + n0 + tx] = hi;
        unpack2(acc_b[p], lo, hi);
        g_att[((size_t)b * HH + 2 * p)     * NN + n0 + 128 + tx] = lo;
        g_att[((size_t)b * HH + 2 * p + 1) * NN + n0 + 128 + tx] = hi;
    }
}

// ---------------------------------------------------------------------------
// Kernel D: in-place softmax over N per (b,h) row.
// ---------------------------------------------------------------------------
__global__ __launch_bounds__(256) void k_softmax() {
    int row = blockIdx.x;
    int tx  = threadIdx.x;
    float4* pv = reinterpret_cast<float4*>(g_att + (size_t)row * NN);

    float4 x[4];
#pragma unroll
    for (int i = 0; i < 4; i++) x[i] = pv[i * 256 + tx];

    float m = -3e38f;
#pragma unroll
    for (int i = 0; i < 4; i++)
        m = fmaxf(m, fmaxf(fmaxf(x[i].x, x[i].y), fmaxf(x[i].z, x[i].w)));
    __shared__ float r1[8], r2[8];
#pragma unroll
    for (int o = 16; o; o >>= 1) m = fmaxf(m, __shfl_xor_sync(0xffffffffu, m, o));
    if ((tx & 31) == 0) r1[tx >> 5] = m;
    __syncthreads();
    float bm = r1[0];
#pragma unroll
    for (int w = 1; w < 8; w++) bm = fmaxf(bm, r1[w]);

    float s = 0.f;
#pragma unroll
    for (int i = 0; i < 4; i++) {
        x[i].x = __expf(x[i].x - bm);
        x[i].y = __expf(x[i].y - bm);
        x[i].z = __expf(x[i].z - bm);
        x[i].w = __expf(x[i].w - bm);
        s += x[i].x + x[i].y + x[i].z + x[i].w;
    }
#pragma unroll
    for (int o = 16; o; o >>= 1) s += __shfl_xor_sync(0xffffffffu, s, o);
    if ((tx & 31) == 0) r2[tx >> 5] = s;
    __syncthreads();
    float tot = 0.f;
#pragma unroll
    for (int w = 0; w < 8; w++) tot += r2[w];
    float inv = 1.f / tot;
#pragma unroll
    for (int i = 0; i < 4; i++) {
        x[i].x *= inv; x[i].y *= inv; x[i].z *= inv; x[i].w *= inv;
        pv[i * 256 + tx] = x[i];
    }
}

// ---------------------------------------------------------------------------
// Kernel E: wp[seg][b,h,d] = sum_{n in seg(512)} attn[b,h,n] * value[b,n,d]
// grid (2 d-tiles of 512, 8 seg, 32 b), 256 thr; thread owns d and d+256.
// att slab staged once; barrier-free mainloop with 4-deep x2 load pipeline.
// ---------------------------------------------------------------------------
__global__ __launch_bounds__(256) void k_wpart(const float* __restrict__ value) {
    const int tx  = threadIdx.x;
    const int d0  = blockIdx.x * 512;
    const int seg = blockIdx.y;
    const int b   = blockIdx.z;

    __shared__ __align__(16) float sA[512 * 20];   // [n][16h + 4 pad], 40KB

    const float* attb = g_att + (size_t)b * HH * NN + seg * 512;
#pragma unroll
    for (int i = 0; i < 32; i++) {
        int fl = i * 256 + tx;
        int h = fl >> 9, n = fl & 511;
        sA[n * 20 + h] = attb[(size_t)h * NN + n];
    }
    __syncthreads();

    u64 acc1[8], acc2[8];
#pragma unroll
    for (int p = 0; p < 8; p++) { acc1[p] = 0ull; acc2[p] = 0ull; }

    const float* v1 = value + ((size_t)b * NN + seg * 512) * DD + d0 + tx;
    const float* v2 = v1 + 256;

    float va[4], vb[4], na[4], nb[4];
#pragma unroll
    for (int j = 0; j < 4; j++) {
        va[j] = __ldcs(v1 + (size_t)j * DD);
        vb[j] = __ldcs(v2 + (size_t)j * DD);
    }

#pragma unroll 1
    for (int n = 0; n < 512; n += 4) {
        if (n + 4 < 512) {
#pragma unroll
            for (int j = 0; j < 4; j++) {
                na[j] = __ldcs(v1 + (size_t)(n + 4 + j) * DD);
                nb[j] = __ldcs(v2 + (size_t)(n + 4 + j) * DD);
            }
        }
#pragma unroll
        for (int j = 0; j < 4; j++) {
            u64 p1 = pack2(va[j], va[j]);
            u64 p2 = pack2(vb[j], vb[j]);
            const ulonglong2* av = (const ulonglong2*)&sA[(n + j) * 20];
            ulonglong2 a0 = av[0], a1 = av[1];
            fma2(acc1[0], a0.x, p1);  fma2(acc2[0], a0.x, p2);
            fma2(acc1[1], a0.y, p1);  fma2(acc2[1], a0.y, p2);
            fma2(acc1[2], a1.x, p1);  fma2(acc2[2], a1.x, p2);
            fma2(acc1[3], a1.y, p1);  fma2(acc2[3], a1.y, p2);
            ulonglong2 a2 = av[2], a3 = av[3];
            fma2(acc1[4], a2.x, p1);  fma2(acc2[4], a2.x, p2);
            fma2(acc1[5], a2.y, p1);  fma2(acc2[5], a2.y, p2);
            fma2(acc1[6], a3.x, p1);  fma2(acc2[6], a3.x, p2);
            fma2(acc1[7], a3.y, p1);  fma2(acc2[7], a3.y, p2);
        }
#pragma unroll
        for (int j = 0; j < 4; j++) { va[j] = na[j]; vb[j] = nb[j]; }
    }

#pragma unroll
    for (int p = 0; p < 8; p++) {
        float lo, hi;
        unpack2(acc1[p], lo, hi);
        g_wp[seg][((size_t)b * HH + 2 * p)     * DD + d0 + tx] = lo;
        g_wp[seg][((size_t)b * HH + 2 * p + 1) * DD + d0 + tx] = hi;
        unpack2(acc2[p], lo, hi);
        g_wp[seg][((size_t)b * HH + 2 * p)     * DD + d0 + 256 + tx] = lo;
        g_wp[seg][((size_t)b * HH + 2 * p + 1) * DD + d0 + 256 + tx] = hi;
    }
}

// ---------------------------------------------------------------------------
// Kernel F: out[b,c] += sum_{d in dsp-range(256)} w[b, c>>6, d] * wv[d, c]
// grid (8 c-tiles, 8 b-groups, 4 d-splits) = 256 blocks, 128 thr.
// Sums the 8 wpart partials during staging; REDG atomicAdd into zeroed d_out.
// ---------------------------------------------------------------------------
__global__ __launch_bounds__(128) void k_oproj(const float* __restrict__ wv,
                                               float* __restrict__ out) {
    const int tx  = threadIdx.x;
    const int c0  = blockIdx.x * 128;
    const int b0  = blockIdx.y * 4;
    const int dsp = blockIdx.z;
    const int dr0 = dsp * 256;
    const int h0  = c0 >> 6;                    // 2 heads in this c-tile
    __shared__ __align__(16) float sw[4][2][256];   // 8KB

#pragma unroll
    for (int i = 0; i < 4; i++) {
        int fl = i * 128 + tx;                  // 512 float4
        int bb = fl >> 7, hh = (fl >> 6) & 1, d4 = fl & 63;
        size_t gidx = ((size_t)(b0 + bb) * HH + h0 + hh) * DD + dr0 + d4 * 4;
        float4 s = *(const float4*)(g_wp[0] + gidx);
#pragma unroll
        for (int p = 1; p < 8; p++) {
            float4 a = *(const float4*)(g_wp[p] + gidx);
            s.x += a.x; s.y += a.y; s.z += a.z; s.w += a.w;
        }
        *(float4*)&sw[bb][hh][d4 * 4] = s;
    }
    __syncthreads();

    const int hin = tx >> 6;
    u64 acc[4] = {0ull, 0ull, 0ull, 0ull};
    const float* wc = wv + (size_t)dr0 * DD + c0 + tx;
#pragma unroll 8
    for (int d = 0; d < 256; d += 2) {
        float w0 = wc[(size_t)d * DD];
        float w1 = wc[(size_t)(d + 1) * DD];
        u64 w2 = pack2(w0, w1);
#pragma unroll
        for (int bb = 0; bb < 4; bb++) {
            u64 s2 = *(const u64*)&sw[bb][hin][d];
            fma2(acc[bb], s2, w2);
        }
    }
#pragma unroll
    for (int bb = 0; bb < 4; bb++) {
        float lo, hi; unpack2(acc[bb], lo, hi);
        atomicAdd(&out[(size_t)(b0 + bb) * DD + c0 + tx], lo + hi);
    }
}

// ---------------------------------------------------------------------------
extern "C" void kernel_launch(void* const* d_in, const int* in_sizes, int n_in,
                              void* d_out, int out_size) {
    const float* query = (const float*)d_in[0];
    const float* key   = (const float*)d_in[1];
    const float* value = (const float*)d_in[2];
    const float* wq    = (const float*)d_in[3];
    const float* wk    = (const float*)d_in[4];
    const float* wv    = (const float*)d_in[5];
    float* out = (float*)d_out;

    k_qproj  <<<dim3(8, 8, 4),  128>>>(query, wq, out);
    k_uproj  <<<dim3(8, HH),    128>>>(wk);
    k_scores <<<dim3(16, BB),   128>>>(key);
    k_softmax<<<BB * HH,        256>>>();
    k_wpart  <<<dim3(2, 8, BB), 256>>>(value);
    k_oproj  <<<dim3(8, 8, 4),  128>>>(wv, out);
}

// round 5
// speedup vs baseline: 1.6861x; 1.1567x over previous
#include <cuda_runtime.h>

#define BB 32
#define NN 4096
#define DD 1024
#define HH 16

// Scratch (device globals)
__device__ float g_qp[4][BB * DD];         // q projection partials over 4 d-ranges
__device__ float g_Ut[BB * DD * HH];       // folded key vectors, transposed [b][d][h] (scaled 1/8)
__device__ float g_att[BB * HH * NN];      // scores -> attn (softmaxed in place)
__device__ float g_wp[8][BB * HH * DD];    // partial attn@value over 8 n-segments

typedef unsigned long long u64;

__device__ __forceinline__ void fma2(u64 &d, u64 a, u64 b) {
    asm("fma.rn.f32x2 %0, %1, %2, %0;" : "+l"(d) : "l"(a), "l"(b));
}
__device__ __forceinline__ u64 pack2(float lo, float hi) {
    u64 r; asm("mov.b64 %0, {%1, %2};" : "=l"(r) : "f"(lo), "f"(hi)); return r;
}
__device__ __forceinline__ void unpack2(u64 v, float &lo, float &hi) {
    asm("mov.b64 {%0, %1}, %2;" : "=f"(lo), "=f"(hi) : "l"(v));
}
__device__ __forceinline__ unsigned smem_u32(const void* p) {
    return (unsigned)__cvta_generic_to_shared(p);
}
__device__ __forceinline__ void cpasync16(unsigned dst, const void* src) {
    asm volatile("cp.async.cg.shared.global [%0], [%1], 16;\n" :: "r"(dst), "l"(src));
}
#define CP_COMMIT() asm volatile("cp.async.commit_group;\n" ::: "memory")
#define CP_WAIT(n)  asm volatile("cp.async.wait_group %0;\n" :: "n"(n) : "memory")

// ---------------------------------------------------------------------------
// Kernel A: qp[dsp][b,c] = sum_{d in dsp-range(256)} query[b,d] * wq[d,c]
// ---------------------------------------------------------------------------
__global__ __launch_bounds__(128) void k_qproj(const float* __restrict__ query,
                                               const float* __restrict__ wq) {
    const int tx  = threadIdx.x;
    const int c0  = blockIdx.x * 128;
    const int b0  = blockIdx.y * 4;
    const int dsp = blockIdx.z;
    const int dr0 = dsp * 256;

    __shared__ __align__(16) float sq[4][256];   // 4KB
#pragma unroll
    for (int i = 0; i < 2; i++) {
        int fl = i * 128 + tx;
        int bb = fl >> 6, d4 = fl & 63;
        *(float4*)&sq[bb][d4 * 4] =
            *(const float4*)(query + (size_t)(b0 + bb) * DD + dr0 + d4 * 4);
    }
    __syncthreads();

    u64 acc[4] = {0ull, 0ull, 0ull, 0ull};
    const float* wc = wq + (size_t)dr0 * DD + c0 + tx;
#pragma unroll 8
    for (int d = 0; d < 256; d += 2) {
        float w0 = wc[(size_t)d * DD];
        float w1 = wc[(size_t)(d + 1) * DD];
        u64 w2 = pack2(w0, w1);
#pragma unroll
        for (int bb = 0; bb < 4; bb++) {
            u64 q2 = *(const u64*)&sq[bb][d];
            fma2(acc[bb], q2, w2);
        }
    }
#pragma unroll
    for (int bb = 0; bb < 4; bb++) {
        float lo, hi; unpack2(acc[bb], lo, hi);
        g_qp[dsp][(size_t)(b0 + bb) * DD + c0 + tx] = lo + hi;
    }
}

// ---------------------------------------------------------------------------
// Kernel B: Ut[b,d,h] = (1/8) * sum_{c<64} wk[d, h*64+c] * q[b, h*64+c]
// ---------------------------------------------------------------------------
__global__ __launch_bounds__(128) void k_uproj(const float* __restrict__ wk) {
    const int tx = threadIdx.x;
    const int d0 = blockIdx.x * 128;
    const int h  = blockIdx.y;
    __shared__ __align__(16) float4 swk4[128 * 17];  // 34.8KB
    __shared__ __align__(16) float  sq[32][64];      // 8KB

#pragma unroll
    for (int i = 0; i < 16; i++) {
        int fl = i * 128 + tx;
        int r  = fl >> 4, c4 = fl & 15;
        swk4[r * 17 + c4] =
            *(const float4*)(wk + (size_t)(d0 + r) * DD + h * 64 + c4 * 4);
    }
#pragma unroll
    for (int i = 0; i < 4; i++) {
        int fl = i * 128 + tx;
        int bb = fl >> 4, c4 = fl & 15;
        float4 s = *(const float4*)(g_qp[0] + (size_t)bb * DD + h * 64 + c4 * 4);
#pragma unroll
        for (int p = 1; p < 4; p++) {
            float4 a = *(const float4*)(g_qp[p] + (size_t)bb * DD + h * 64 + c4 * 4);
            s.x += a.x; s.y += a.y; s.z += a.z; s.w += a.w;
        }
        *(float4*)&sq[bb][c4 * 4] = s;
    }
    __syncthreads();

    ulonglong2 wreg[16];
#pragma unroll
    for (int c4 = 0; c4 < 16; c4++)
        wreg[c4] = *(const ulonglong2*)&swk4[tx * 17 + c4];

    const int dst_base = (d0 + tx) * HH + h;
#pragma unroll 2
    for (int bb = 0; bb < 32; bb++) {
        u64 a2 = 0ull;
#pragma unroll
        for (int c4 = 0; c4 < 16; c4++) {
            ulonglong2 q2 = *(const ulonglong2*)&sq[bb][c4 * 4];
            fma2(a2, wreg[c4].x, q2.x);
            fma2(a2, wreg[c4].y, q2.y);
        }
        float lo, hi; unpack2(a2, lo, hi);
        g_Ut[(size_t)bb * (DD * HH) + dst_base] = (lo + hi) * 0.125f;
    }
}

// ---------------------------------------------------------------------------
// Kernel Z: zero d_out (for oproj atomics). Also shifts the ncu profile slot.
// ---------------------------------------------------------------------------
__global__ __launch_bounds__(256) void k_zero(float* __restrict__ out) {
    int i = blockIdx.x * 256 + threadIdx.x;   // 8192 float4 = 32 blocks
    reinterpret_cast<float4*>(out)[i] = make_float4(0.f, 0.f, 0.f, 0.f);
}

// ---------------------------------------------------------------------------
// Kernel C: scores[b,h,n] = sum_d key[b,n,d] * Ut[b,d,h]   (streams key 512MB)
// BARRIER-FREE: each warp owns a private 64-n smem slab + private U replica;
// cp.async pipelining is per-warp (commit/wait are per-thread) -> only
// __syncwarp in the 64-chunk mainloop. Thread owns n = w*64 + l and +32.
// ---------------------------------------------------------------------------
__global__ __launch_bounds__(128) void k_scores(const float* __restrict__ key) {
    const int tx   = threadIdx.x;
    const int w    = tx >> 5;
    const int l    = tx & 31;
    const int b    = blockIdx.y;
    const int n0   = blockIdx.x * 256;
    const int nwrp = n0 + w * 64;

    // per-warp, per-stage private slabs. Row stride 5 float4 (gcd(5,8)=1 ->
    // conflict-free LDS.128 at n=l and n=l+32).
    __shared__ __align__(16) float4 skW[4][2][64 * 5];  // 40KB
    __shared__ __align__(16) float4 sUW[4][2][64];      // 8KB

    const float* keyw = key + ((size_t)b * NN + nwrp) * DD;
    const float* Utbb = g_Ut + (size_t)b * (DD * HH);

    u64 acc_a[8], acc_b[8];
#pragma unroll
    for (int p = 0; p < 8; p++) { acc_a[p] = 0ull; acc_b[p] = 0ull; }

    // prologue: issue chunk 0 (d 0..15)
    {
#pragma unroll
        for (int i = 0; i < 8; i++) {
            int fl = i * 32 + l;
            int n = fl >> 2, q4 = fl & 3;
            cpasync16(smem_u32(&skW[w][0][n * 5 + q4]),
                      keyw + (size_t)n * DD + q4 * 4);
        }
#pragma unroll
        for (int j = 0; j < 2; j++)
            cpasync16(smem_u32(&sUW[w][0][j * 32 + l]), Utbb + (j * 32 + l) * 4);
        CP_COMMIT();
    }

#pragma unroll 1
    for (int ch = 0; ch < 64; ch++) {
        if (ch + 1 < 64) {
            const int st = (ch + 1) & 1, d0 = (ch + 1) * 16;
#pragma unroll
            for (int i = 0; i < 8; i++) {
                int fl = i * 32 + l;
                int n = fl >> 2, q4 = fl & 3;
                cpasync16(smem_u32(&skW[w][st][n * 5 + q4]),
                          keyw + (size_t)n * DD + d0 + q4 * 4);
            }
#pragma unroll
            for (int j = 0; j < 2; j++)
                cpasync16(smem_u32(&sUW[w][st][j * 32 + l]),
                          Utbb + d0 * HH + (j * 32 + l) * 4);
            CP_COMMIT();
            CP_WAIT(1);
        } else {
            CP_WAIT(0);
        }
        __syncwarp();

        const int st = ch & 1;
#pragma unroll
        for (int g = 0; g < 4; g++) {
            float4 ka = skW[w][st][l * 5 + g];
            float4 kb = skW[w][st][(l + 32) * 5 + g];
            float kas[4] = {ka.x, ka.y, ka.z, ka.w};
            float kbs[4] = {kb.x, kb.y, kb.z, kb.w};
#pragma unroll
            for (int s = 0; s < 4; s++) {
                int dd = g * 4 + s;
                u64 kva = pack2(kas[s], kas[s]);
                u64 kvb = pack2(kbs[s], kbs[s]);
                const ulonglong2* uv = (const ulonglong2*)&sUW[w][st][dd * 4];
                ulonglong2 u0 = uv[0], u1 = uv[1];
                fma2(acc_a[0], u0.x, kva);  fma2(acc_b[0], u0.x, kvb);
                fma2(acc_a[1], u0.y, kva);  fma2(acc_b[1], u0.y, kvb);
                fma2(acc_a[2], u1.x, kva);  fma2(acc_b[2], u1.x, kvb);
                fma2(acc_a[3], u1.y, kva);  fma2(acc_b[3], u1.y, kvb);
                ulonglong2 u2 = uv[2], u3 = uv[3];
                fma2(acc_a[4], u2.x, kva);  fma2(acc_b[4], u2.x, kvb);
                fma2(acc_a[5], u2.y, kva);  fma2(acc_b[5], u2.y, kvb);
                fma2(acc_a[6], u3.x, kva);  fma2(acc_b[6], u3.x, kvb);
                fma2(acc_a[7], u3.y, kva);  fma2(acc_b[7], u3.y, kvb);
            }
        }
        __syncwarp();
    }

#pragma unroll
    for (int p = 0; p < 8; p++) {
        float lo, hi;
        unpack2(acc_a[p], lo, hi);
        g_att[((size_t)b * HH + 2 * p)     * NN + nwrp + l] = lo;
        g_att[((size_t)b * HH + 2 * p + 1) * NN + nwrp + l] = hi;
        unpack2(acc_b[p], lo, hi);
        g_att[((size_t)b * HH + 2 * p)     * NN + nwrp + 32 + l] = lo;
        g_att[((size_t)b * HH + 2 * p + 1) * NN + nwrp + 32 + l] = hi;
    }
}

// ---------------------------------------------------------------------------
// Kernel D: in-place softmax over N per (b,h) row.
// ---------------------------------------------------------------------------
__global__ __launch_bounds__(256) void k_softmax() {
    int row = blockIdx.x;
    int tx  = threadIdx.x;
    float4* pv = reinterpret_cast<float4*>(g_att + (size_t)row * NN);

    float4 x[4];
#pragma unroll
    for (int i = 0; i < 4; i++) x[i] = pv[i * 256 + tx];

    float m = -3e38f;
#pragma unroll
    for (int i = 0; i < 4; i++)
        m = fmaxf(m, fmaxf(fmaxf(x[i].x, x[i].y), fmaxf(x[i].z, x[i].w)));
    __shared__ float r1[8], r2[8];
#pragma unroll
    for (int o = 16; o; o >>= 1) m = fmaxf(m, __shfl_xor_sync(0xffffffffu, m, o));
    if ((tx & 31) == 0) r1[tx >> 5] = m;
    __syncthreads();
    float bm = r1[0];
#pragma unroll
    for (int w = 1; w < 8; w++) bm = fmaxf(bm, r1[w]);

    float s = 0.f;
#pragma unroll
    for (int i = 0; i < 4; i++) {
        x[i].x = __expf(x[i].x - bm);
        x[i].y = __expf(x[i].y - bm);
        x[i].z = __expf(x[i].z - bm);
        x[i].w = __expf(x[i].w - bm);
        s += x[i].x + x[i].y + x[i].z + x[i].w;
    }
#pragma unroll
    for (int o = 16; o; o >>= 1) s += __shfl_xor_sync(0xffffffffu, s, o);
    if ((tx & 31) == 0) r2[tx >> 5] = s;
    __syncthreads();
    float tot = 0.f;
#pragma unroll
    for (int w = 0; w < 8; w++) tot += r2[w];
    float inv = 1.f / tot;
#pragma unroll
    for (int i = 0; i < 4; i++) {
        x[i].x *= inv; x[i].y *= inv; x[i].z *= inv; x[i].w *= inv;
        pv[i * 256 + tx] = x[i];
    }
}

// ---------------------------------------------------------------------------
// Kernel E: wp[seg][b,h,d] = sum_{n in seg(512)} attn[b,h,n] * value[b,n,d]
// grid (2 d-tiles of 512, 8 seg, 32 b), 128 thr; thread owns 4 consecutive d
// (float4 LDG.128 of value). FMA2 lanes pair (d,d+1). STG.128 epilogue.
// ---------------------------------------------------------------------------
__global__ __launch_bounds__(128) void k_wpart(const float* __restrict__ value) {
    const int tx  = threadIdx.x;
    const int d0  = blockIdx.x * 512;
    const int seg = blockIdx.y;
    const int b   = blockIdx.z;

    __shared__ __align__(16) float sA[512 * 20];   // [n][16h + 4 pad], 40KB

    const float* attb = g_att + (size_t)b * HH * NN + seg * 512;
#pragma unroll
    for (int i = 0; i < 16; i++) {
        int fl = i * 128 + tx;          // 2048 float4 of g_att
        int h = fl >> 7, n4 = (fl & 127) * 4;
        float4 a = *(const float4*)(attb + (size_t)h * NN + n4);
        sA[(n4 + 0) * 20 + h] = a.x;
        sA[(n4 + 1) * 20 + h] = a.y;
        sA[(n4 + 2) * 20 + h] = a.z;
        sA[(n4 + 3) * 20 + h] = a.w;
    }
    __syncthreads();

    u64 acc[32];   // [dpair(2)][hp(8)] x2 halves: idx = dp*16 ... use [dd-pair][hp]
#pragma unroll
    for (int p = 0; p < 32; p++) acc[p] = 0ull;
    // acc[dp*8+hp]: dp=0 -> lanes (d0+tx*4+0, +1)? No: head-pairing:
    // acc[dd*8+hp] with dd in 0..3 (the 4 d this thread owns), hp in 0..7.

    const float* valb = value + ((size_t)b * NN + seg * 512) * DD + d0 + tx * 4;

    float4 vc[4], vn[4];
#pragma unroll
    for (int j = 0; j < 4; j++)
        vc[j] = *(const float4*)(valb + (size_t)j * DD);

#pragma unroll 1
    for (int n = 0; n < 512; n += 4) {
        if (n + 4 < 512) {
#pragma unroll
            for (int j = 0; j < 4; j++)
                vn[j] = *(const float4*)(valb + (size_t)(n + 4 + j) * DD);
        }
#pragma unroll
        for (int j = 0; j < 4; j++) {
            float vs[4] = {vc[j].x, vc[j].y, vc[j].z, vc[j].w};
            const ulonglong2* av = (const ulonglong2*)&sA[(n + j) * 20];
            ulonglong2 a0 = av[0], a1 = av[1], a2 = av[2], a3 = av[3];
#pragma unroll
            for (int dd = 0; dd < 4; dd++) {
                u64 v2 = pack2(vs[dd], vs[dd]);
                fma2(acc[dd * 8 + 0], a0.x, v2);
                fma2(acc[dd * 8 + 1], a0.y, v2);
                fma2(acc[dd * 8 + 2], a1.x, v2);
                fma2(acc[dd * 8 + 3], a1.y, v2);
                fma2(acc[dd * 8 + 4], a2.x, v2);
                fma2(acc[dd * 8 + 5], a2.y, v2);
                fma2(acc[dd * 8 + 6], a3.x, v2);
                fma2(acc[dd * 8 + 7], a3.y, v2);
            }
        }
#pragma unroll
        for (int j = 0; j < 4; j++) vc[j] = vn[j];
    }

    // epilogue: per head build float4 over the 4 d and STG.128
#pragma unroll
    for (int hp = 0; hp < 8; hp++) {
        float4 olo, ohi;
        float l0, h0x, l1, h1x, l2, h2x, l3, h3x;
        unpack2(acc[0 * 8 + hp], l0, h0x);
        unpack2(acc[1 * 8 + hp], l1, h1x);
        unpack2(acc[2 * 8 + hp], l2, h2x);
        unpack2(acc[3 * 8 + hp], l3, h3x);
        olo = make_float4(l0, l1, l2, l3);
        ohi = make_float4(h0x, h1x, h2x, h3x);
        *(float4*)(g_wp[seg] + ((size_t)b * HH + 2 * hp)     * DD + d0 + tx * 4) = olo;
        *(float4*)(g_wp[seg] + ((size_t)b * HH + 2 * hp + 1) * DD + d0 + tx * 4) = ohi;
    }
}

// ---------------------------------------------------------------------------
// Kernel F: out[b,c] += sum_{d in dsp-range(256)} w[b, c>>6, d] * wv[d, c]
// ---------------------------------------------------------------------------
__global__ __launch_bounds__(128) void k_oproj(const float* __restrict__ wv,
                                               float* __restrict__ out) {
    const int tx  = threadIdx.x;
    const int c0  = blockIdx.x * 128;
    const int b0  = blockIdx.y * 4;
    const int dsp = blockIdx.z;
    const int dr0 = dsp * 256;
    const int h0  = c0 >> 6;
    __shared__ __align__(16) float sw[4][2][256];   // 8KB

#pragma unroll
    for (int i = 0; i < 4; i++) {
        int fl = i * 128 + tx;
        int bb = fl >> 7, hh = (fl >> 6) & 1, d4 = fl & 63;
        size_t gidx = ((size_t)(b0 + bb) * HH + h0 + hh) * DD + dr0 + d4 * 4;
        float4 s = *(const float4*)(g_wp[0] + gidx);
#pragma unroll
        for (int p = 1; p < 8; p++) {
            float4 a = *(const float4*)(g_wp[p] + gidx);
            s.x += a.x; s.y += a.y; s.z += a.z; s.w += a.w;
        }
        *(float4*)&sw[bb][hh][d4 * 4] = s;
    }
    __syncthreads();

    const int hin = tx >> 6;
    u64 acc[4] = {0ull, 0ull, 0ull, 0ull};
    const float* wc = wv + (size_t)dr0 * DD + c0 + tx;
#pragma unroll 8
    for (int d = 0; d < 256; d += 2) {
        float w0 = wc[(size_t)d * DD];
        float w1 = wc[(size_t)(d + 1) * DD];
        u64 w2 = pack2(w0, w1);
#pragma unroll
        for (int bb = 0; bb < 4; bb++) {
            u64 s2 = *(const u64*)&sw[bb][hin][d];
            fma2(acc[bb], s2, w2);
        }
    }
#pragma unroll
    for (int bb = 0; bb < 4; bb++) {
        float lo, hi; unpack2(acc[bb], lo, hi);
        atomicAdd(&out[(size_t)(b0 + bb) * DD + c0 + tx], lo + hi);
    }
}

// ---------------------------------------------------------------------------
extern "C" void kernel_launch(void* const* d_in, const int* in_sizes, int n_in,
                              void* d_out, int out_size) {
    const float* query = (const float*)d_in[0];
    const float* key   = (const float*)d_in[1];
    const float* value = (const float*)d_in[2];
    const float* wq    = (const float*)d_in[3];
    const float* wk    = (const float*)d_in[4];
    const float* wv    = (const float*)d_in[5];
    float* out = (float*)d_out;

    k_qproj  <<<dim3(8, 8, 4),  128>>>(query, wq);
    k_uproj  <<<dim3(8, HH),    128>>>(wk);
    k_zero   <<<32,             256>>>(out);
    k_scores <<<dim3(16, BB),   128>>>(key);
    k_softmax<<<BB * HH,        256>>>();
    k_wpart  <<<dim3(2, 8, BB), 128>>>(value);
    k_oproj  <<<dim3(8, 8, 4),  128>>>(wv, out);
}